// round 2
// baseline (speedup 1.0000x reference)
#include <cuda_runtime.h>
#include <cuda_bf16.h>
#include <math.h>

// Problem constants (from reference): B=4, S=2048 -> T=8192 tokens
#define T_TOK 8192
#define DDIM  1024
#define FDIM  2048
#define NE    8
#define TOPK  2
#define NPAIR (T_TOK * TOPK)   // 16384

// ---------------- scratch (static device globals; no allocs allowed) -------
__device__ int   g_cnt[NE];
__device__ int   g_off[NE];
__device__ int   g_tok[NE * T_TOK];   // token id per (expert, local row)
__device__ int   g_dst[NE * T_TOK];   // destination pair slot = 2*t + k
__device__ float g_wp [NE * T_TOK];   // combine weight for that pair
__device__ float g_H  [(size_t)NPAIR * FDIM];   // 128 MiB intermediate
__device__ float g_pout[(size_t)NPAIR * DDIM];  // 64 MiB per-pair down-proj

// ---------------- small kernels -------------------------------------------
__global__ void zero_cnt_kernel() {
    if (threadIdx.x < NE) g_cnt[threadIdx.x] = 0;
}

__global__ void offsets_kernel() {
    if (threadIdx.x == 0) {
        int acc = 0;
        for (int e = 0; e < NE; e++) { g_off[e] = acc; acc += g_cnt[e]; }
    }
}

// Router: logits = x @ gate_w + gate_b; top-2 of softmax; normalized weights.
// One warp per token. Writes raw logits to d_out tail, fills expert lists.
__global__ __launch_bounds__(256) void router_kernel(
    const float* __restrict__ x, const float* __restrict__ gate_w,
    const float* __restrict__ gate_b, float* __restrict__ logits_out,
    int write_logits)
{
    int warp = threadIdx.x >> 5, lane = threadIdx.x & 31;
    int t = blockIdx.x * 8 + warp;
    if (t >= T_TOK) return;

    float acc[NE];
#pragma unroll
    for (int e = 0; e < NE; e++) acc[e] = 0.f;

    const float* xr = x + (size_t)t * DDIM;
    for (int d = lane; d < DDIM; d += 32) {
        float xv = xr[d];
        const float4* g4 = (const float4*)(gate_w + (size_t)d * NE);
        float4 g0 = g4[0], g1 = g4[1];
        acc[0] += xv * g0.x; acc[1] += xv * g0.y;
        acc[2] += xv * g0.z; acc[3] += xv * g0.w;
        acc[4] += xv * g1.x; acc[5] += xv * g1.y;
        acc[6] += xv * g1.z; acc[7] += xv * g1.w;
    }
#pragma unroll
    for (int e = 0; e < NE; e++) {
#pragma unroll
        for (int s = 16; s > 0; s >>= 1)
            acc[e] += __shfl_xor_sync(0xFFFFFFFFu, acc[e], s);
    }

    if (lane == 0) {
        float l[NE];
#pragma unroll
        for (int e = 0; e < NE; e++) l[e] = acc[e] + gate_b[e];
        if (write_logits) {
#pragma unroll
            for (int e = 0; e < NE; e++) logits_out[(size_t)t * NE + e] = l[e];
        }
        // top-2 (first index wins ties, matching jax top_k)
        int i0 = 0;
#pragma unroll
        for (int e = 1; e < NE; e++) if (l[e] > l[i0]) i0 = e;
        int i1 = (i0 == 0) ? 1 : 0;
#pragma unroll
        for (int e = 0; e < NE; e++) if (e != i0 && l[e] > l[i1]) i1 = e;

        // normalized top-2 softmax weights: w0 = p0/(p0+p1)
        float w0 = 1.0f / (1.0f + expf(l[i1] - l[i0]));
        float w1 = 1.0f - w0;

        int p0 = atomicAdd(&g_cnt[i0], 1);
        g_tok[i0 * T_TOK + p0] = t;
        g_dst[i0 * T_TOK + p0] = 2 * t + 0;
        g_wp [i0 * T_TOK + p0] = w0;

        int p1 = atomicAdd(&g_cnt[i1], 1);
        g_tok[i1 * T_TOK + p1] = t;
        g_dst[i1 * T_TOK + p1] = 2 * t + 1;
        g_wp [i1 * T_TOK + p1] = w1;
    }
}

// ---------------- GEMM1: H = silu(X@Wg + bg) * (X@Wu + bu), gathered rows --
// 64x64 tile, k-tile 16, 256 threads, 4x4 micro-tile, dual accumulators.
__global__ __launch_bounds__(256) void gemm1_kernel(
    const float* __restrict__ x,
    const float* __restrict__ Wg, const float* __restrict__ bg,
    const float* __restrict__ Wu, const float* __restrict__ bu)
{
    int e = blockIdx.z;
    int cnt = g_cnt[e];
    int row0 = blockIdx.y * 64;
    if (row0 >= cnt) return;
    int col0 = blockIdx.x * 64;

    __shared__ float sX[16][64];   // [k][m]
    __shared__ float sG[16][64];   // [k][n]
    __shared__ float sU[16][64];   // [k][n]
    __shared__ int   stok[64];

    int tid = threadIdx.x;
    if (tid < 64) {
        int r = row0 + tid;
        stok[tid] = g_tok[e * T_TOK + min(r, cnt - 1)];
    }
    __syncthreads();

    const float* WgE = Wg + (size_t)e * DDIM * FDIM;
    const float* WuE = Wu + (size_t)e * DDIM * FDIM;

    float accG[4][4], accU[4][4];
#pragma unroll
    for (int i = 0; i < 4; i++)
#pragma unroll
        for (int j = 0; j < 4; j++) { accG[i][j] = 0.f; accU[i][j] = 0.f; }

    int ty = tid >> 4, tx = tid & 15;
    int lm = tid >> 2;              // X-load row (0..63)
    int lk = (tid & 3) * 4;         // X-load k   (0,4,8,12)
    int wk = tid >> 6;              // W-load k   (0..3)
    int wn = (tid & 63);            // W-load n via *4 pattern below

    for (int kb = 0; kb < DDIM; kb += 16) {
        {   // X tile: gathered token rows, stored transposed
            float4 v = *(const float4*)(x + (size_t)stok[lm] * DDIM + kb + lk);
            sX[lk + 0][lm] = v.x; sX[lk + 1][lm] = v.y;
            sX[lk + 2][lm] = v.z; sX[lk + 3][lm] = v.w;
        }
        {   // W tiles: idx = tid*4 -> k = idx/64, n = idx%64
            int idx = tid * 4;
            int k = idx >> 6, n = idx & 63;
            *(float4*)&sG[k][n] = *(const float4*)(WgE + (size_t)(kb + k) * FDIM + col0 + n);
            *(float4*)&sU[k][n] = *(const float4*)(WuE + (size_t)(kb + k) * FDIM + col0 + n);
        }
        __syncthreads();
#pragma unroll
        for (int k = 0; k < 16; k++) {
            float a[4], bG[4], bU[4];
            *(float4*)a  = *(const float4*)&sX[k][ty * 4];
            *(float4*)bG = *(const float4*)&sG[k][tx * 4];
            *(float4*)bU = *(const float4*)&sU[k][tx * 4];
#pragma unroll
            for (int i = 0; i < 4; i++)
#pragma unroll
                for (int j = 0; j < 4; j++) {
                    accG[i][j] += a[i] * bG[j];
                    accU[i][j] += a[i] * bU[j];
                }
        }
        __syncthreads();
    }
    (void)wk; (void)wn;

    int base = g_off[e];
#pragma unroll
    for (int i = 0; i < 4; i++) {
        int r = row0 + ty * 4 + i;
        if (r >= cnt) break;
        float* Hrow = g_H + (size_t)(base + r) * FDIM + col0;
        float4 hv;
        float* hp = (float*)&hv;
#pragma unroll
        for (int j = 0; j < 4; j++) {
            int n = col0 + tx * 4 + j;
            float a = accG[i][j] + bg[e * FDIM + n];
            float b = accU[i][j] + bu[e * FDIM + n];
            float s = a / (1.0f + expf(-a));   // silu
            hp[j] = s * b;
        }
        *(float4*)&Hrow[tx * 4] = hv;
    }
}

// ---------------- GEMM2: pout[dst] = w * (H_e @ Wd[e] + bd[e]) -------------
__global__ __launch_bounds__(256) void gemm2_kernel(
    const float* __restrict__ Wd, const float* __restrict__ bd)
{
    int e = blockIdx.z;
    int cnt = g_cnt[e];
    int row0 = blockIdx.y * 64;
    if (row0 >= cnt) return;
    int col0 = blockIdx.x * 64;

    __shared__ float sH[16][64];
    __shared__ float sW[16][64];

    int tid = threadIdx.x;
    int ty = tid >> 4, tx = tid & 15;
    int base = g_off[e];
    const float* WdE = Wd + (size_t)e * FDIM * DDIM;

    float acc[4][4];
#pragma unroll
    for (int i = 0; i < 4; i++)
#pragma unroll
        for (int j = 0; j < 4; j++) acc[i][j] = 0.f;

    int lm = tid >> 2;
    int lk = (tid & 3) * 4;

    for (int kb = 0; kb < FDIM; kb += 16) {
        {
            int r = min(row0 + lm, cnt - 1);
            float4 v = *(const float4*)(g_H + (size_t)(base + r) * FDIM + kb + lk);
            sH[lk + 0][lm] = v.x; sH[lk + 1][lm] = v.y;
            sH[lk + 2][lm] = v.z; sH[lk + 3][lm] = v.w;
        }
        {
            int idx = tid * 4;
            int k = idx >> 6, n = idx & 63;
            *(float4*)&sW[k][n] = *(const float4*)(WdE + (size_t)(kb + k) * DDIM + col0 + n);
        }
        __syncthreads();
#pragma unroll
        for (int k = 0; k < 16; k++) {
            float a[4], b[4];
            *(float4*)a = *(const float4*)&sH[k][ty * 4];
            *(float4*)b = *(const float4*)&sW[k][tx * 4];
#pragma unroll
            for (int i = 0; i < 4; i++)
#pragma unroll
                for (int j = 0; j < 4; j++) acc[i][j] += a[i] * b[j];
        }
        __syncthreads();
    }

#pragma unroll
    for (int i = 0; i < 4; i++) {
        int r = row0 + ty * 4 + i;
        if (r >= cnt) break;
        float w  = g_wp [e * T_TOK + r];
        int  dst = g_dst[e * T_TOK + r];
        float* orow = g_pout + (size_t)dst * DDIM + col0;
        float4 ov;
        float* op = (float*)&ov;
#pragma unroll
        for (int j = 0; j < 4; j++) {
            int n = col0 + tx * 4 + j;
            op[j] = w * (acc[i][j] + bd[e * DDIM + n]);
        }
        *(float4*)&orow[tx * 4] = ov;
    }
}

// ---------------- combine: out[t] = pout[2t] + pout[2t+1] ------------------
__global__ __launch_bounds__(256) void combine_kernel(float* __restrict__ out)
{
    size_t v = (size_t)blockIdx.x * blockDim.x + threadIdx.x;  // float4 index
    size_t t = v / (DDIM / 4);
    size_t c = v % (DDIM / 4);
    if (t >= T_TOK) return;
    const float4* p0 = (const float4*)(g_pout + (2 * t)     * (size_t)DDIM) + c;
    const float4* p1 = (const float4*)(g_pout + (2 * t + 1) * (size_t)DDIM) + c;
    float4 a = *p0, b = *p1;
    float4 o;
    o.x = a.x + b.x; o.y = a.y + b.y; o.z = a.z + b.z; o.w = a.w + b.w;
    ((float4*)out)[v] = o;
}

// ---------------- launch ---------------------------------------------------
extern "C" void kernel_launch(void* const* d_in, const int* in_sizes, int n_in,
                              void* d_out, int out_size)
{
    const float* x      = (const float*)d_in[0];
    const float* gate_w = (const float*)d_in[1];
    const float* gate_b = (const float*)d_in[2];
    const float* Wg     = (const float*)d_in[3];
    const float* bg     = (const float*)d_in[4];
    const float* Wu     = (const float*)d_in[5];
    const float* bu     = (const float*)d_in[6];
    const float* Wd     = (const float*)d_in[7];
    const float* bd     = (const float*)d_in[8];
    float* out = (float*)d_out;

    int write_logits = (out_size >= T_TOK * DDIM + T_TOK * NE) ? 1 : 0;

    zero_cnt_kernel<<<1, 32>>>();
    router_kernel<<<T_TOK / 8, 256>>>(x, gate_w, gate_b,
                                      out + (size_t)T_TOK * DDIM, write_logits);
    offsets_kernel<<<1, 32>>>();
    gemm1_kernel<<<dim3(FDIM / 64, T_TOK / 64, NE), 256>>>(x, Wg, bg, Wu, bu);
    gemm2_kernel<<<dim3(DDIM / 64, T_TOK / 64, NE), 256>>>(Wd, bd);
    combine_kernel<<<(T_TOK * (DDIM / 4)) / 256, 256>>>(out);
}

// round 3
// speedup vs baseline: 1.0010x; 1.0010x over previous
#include <cuda_runtime.h>
#include <cuda_bf16.h>
#include <math.h>

// Problem constants (from reference): B=4, S=2048 -> T=8192 tokens
#define T_TOK 8192
#define DDIM  1024
#define FDIM  2048
#define NE    8
#define TOPK  2
#define NPAIR (T_TOK * TOPK)   // 16384

// ---------------- scratch (static device globals; no allocs allowed) -------
__device__ int   g_cnt[NE];
__device__ int   g_off[NE];
__device__ int   g_tok[NE * T_TOK];   // token id per (expert, local row)
__device__ int   g_dst[NE * T_TOK];   // destination pair slot = 2*t + k
__device__ float g_wp [NE * T_TOK];   // combine weight for that pair
__device__ float g_H  [(size_t)NPAIR * FDIM];   // 128 MiB intermediate
__device__ float g_pout[(size_t)NPAIR * DDIM];  // 64 MiB per-pair down-proj

// ---------------- small kernels -------------------------------------------
__global__ void zero_cnt_kernel() {
    if (threadIdx.x < NE) g_cnt[threadIdx.x] = 0;
}

__global__ void offsets_kernel() {
    if (threadIdx.x == 0) {
        int acc = 0;
        for (int e = 0; e < NE; e++) { g_off[e] = acc; acc += g_cnt[e]; }
    }
}

// Router: logits = x @ gate_w + gate_b; top-2 of softmax; normalized weights.
// One warp per token. Writes raw logits to d_out tail, fills expert lists.
__global__ __launch_bounds__(256) void router_kernel(
    const float* __restrict__ x, const float* __restrict__ gate_w,
    const float* __restrict__ gate_b, float* __restrict__ logits_out,
    int write_logits)
{
    int warp = threadIdx.x >> 5, lane = threadIdx.x & 31;
    int t = blockIdx.x * 8 + warp;
    if (t >= T_TOK) return;

    float acc[NE];
#pragma unroll
    for (int e = 0; e < NE; e++) acc[e] = 0.f;

    const float* xr = x + (size_t)t * DDIM;
    for (int d = lane; d < DDIM; d += 32) {
        float xv = xr[d];
        const float4* g4 = (const float4*)(gate_w + (size_t)d * NE);
        float4 g0 = g4[0], g1 = g4[1];
        acc[0] += xv * g0.x; acc[1] += xv * g0.y;
        acc[2] += xv * g0.z; acc[3] += xv * g0.w;
        acc[4] += xv * g1.x; acc[5] += xv * g1.y;
        acc[6] += xv * g1.z; acc[7] += xv * g1.w;
    }
#pragma unroll
    for (int e = 0; e < NE; e++) {
#pragma unroll
        for (int s = 16; s > 0; s >>= 1)
            acc[e] += __shfl_xor_sync(0xFFFFFFFFu, acc[e], s);
    }

    if (lane == 0) {
        float l[NE];
#pragma unroll
        for (int e = 0; e < NE; e++) l[e] = acc[e] + gate_b[e];
        if (write_logits) {
#pragma unroll
            for (int e = 0; e < NE; e++) logits_out[(size_t)t * NE + e] = l[e];
        }
        // top-2 (first index wins ties, matching jax top_k)
        int i0 = 0;
#pragma unroll
        for (int e = 1; e < NE; e++) if (l[e] > l[i0]) i0 = e;
        int i1 = (i0 == 0) ? 1 : 0;
#pragma unroll
        for (int e = 0; e < NE; e++) if (e != i0 && l[e] > l[i1]) i1 = e;

        // normalized top-2 softmax weights: w0 = p0/(p0+p1)
        float w0 = 1.0f / (1.0f + expf(l[i1] - l[i0]));
        float w1 = 1.0f - w0;

        int p0 = atomicAdd(&g_cnt[i0], 1);
        g_tok[i0 * T_TOK + p0] = t;
        g_dst[i0 * T_TOK + p0] = 2 * t + 0;
        g_wp [i0 * T_TOK + p0] = w0;

        int p1 = atomicAdd(&g_cnt[i1], 1);
        g_tok[i1 * T_TOK + p1] = t;
        g_dst[i1 * T_TOK + p1] = 2 * t + 1;
        g_wp [i1 * T_TOK + p1] = w1;
    }
}

// ---------------- GEMM1: H = silu(X@Wg + bg) * (X@Wu + bu), gathered rows --
// 64x64 tile, k-tile 16, 256 threads, 4x4 micro-tile, dual accumulators.
__global__ __launch_bounds__(256) void gemm1_kernel(
    const float* __restrict__ x,
    const float* __restrict__ Wg, const float* __restrict__ bg,
    const float* __restrict__ Wu, const float* __restrict__ bu)
{
    int e = blockIdx.z;
    int cnt = g_cnt[e];
    int row0 = blockIdx.y * 64;
    if (row0 >= cnt) return;
    int col0 = blockIdx.x * 64;

    __shared__ float sX[16][64];   // [k][m]
    __shared__ float sG[16][64];   // [k][n]
    __shared__ float sU[16][64];   // [k][n]
    __shared__ int   stok[64];

    int tid = threadIdx.x;
    if (tid < 64) {
        int r = row0 + tid;
        stok[tid] = g_tok[e * T_TOK + min(r, cnt - 1)];
    }
    __syncthreads();

    const float* WgE = Wg + (size_t)e * DDIM * FDIM;
    const float* WuE = Wu + (size_t)e * DDIM * FDIM;

    float accG[4][4], accU[4][4];
#pragma unroll
    for (int i = 0; i < 4; i++)
#pragma unroll
        for (int j = 0; j < 4; j++) { accG[i][j] = 0.f; accU[i][j] = 0.f; }

    int ty = tid >> 4, tx = tid & 15;
    int lm = tid >> 2;              // X-load row (0..63)
    int lk = (tid & 3) * 4;         // X-load k   (0,4,8,12)
    int wk = tid >> 6;              // W-load k   (0..3)
    int wn = (tid & 63);            // W-load n via *4 pattern below

    for (int kb = 0; kb < DDIM; kb += 16) {
        {   // X tile: gathered token rows, stored transposed
            float4 v = *(const float4*)(x + (size_t)stok[lm] * DDIM + kb + lk);
            sX[lk + 0][lm] = v.x; sX[lk + 1][lm] = v.y;
            sX[lk + 2][lm] = v.z; sX[lk + 3][lm] = v.w;
        }
        {   // W tiles: idx = tid*4 -> k = idx/64, n = idx%64
            int idx = tid * 4;
            int k = idx >> 6, n = idx & 63;
            *(float4*)&sG[k][n] = *(const float4*)(WgE + (size_t)(kb + k) * FDIM + col0 + n);
            *(float4*)&sU[k][n] = *(const float4*)(WuE + (size_t)(kb + k) * FDIM + col0 + n);
        }
        __syncthreads();
#pragma unroll
        for (int k = 0; k < 16; k++) {
            float a[4], bG[4], bU[4];
            *(float4*)a  = *(const float4*)&sX[k][ty * 4];
            *(float4*)bG = *(const float4*)&sG[k][tx * 4];
            *(float4*)bU = *(const float4*)&sU[k][tx * 4];
#pragma unroll
            for (int i = 0; i < 4; i++)
#pragma unroll
                for (int j = 0; j < 4; j++) {
                    accG[i][j] += a[i] * bG[j];
                    accU[i][j] += a[i] * bU[j];
                }
        }
        __syncthreads();
    }
    (void)wk; (void)wn;

    int base = g_off[e];
#pragma unroll
    for (int i = 0; i < 4; i++) {
        int r = row0 + ty * 4 + i;
        if (r >= cnt) break;
        float* Hrow = g_H + (size_t)(base + r) * FDIM + col0;
        float4 hv;
        float* hp = (float*)&hv;
#pragma unroll
        for (int j = 0; j < 4; j++) {
            int n = col0 + tx * 4 + j;
            float a = accG[i][j] + bg[e * FDIM + n];
            float b = accU[i][j] + bu[e * FDIM + n];
            float s = a / (1.0f + expf(-a));   // silu
            hp[j] = s * b;
        }
        *(float4*)&Hrow[tx * 4] = hv;
    }
}

// ---------------- GEMM2: pout[dst] = w * (H_e @ Wd[e] + bd[e]) -------------
__global__ __launch_bounds__(256) void gemm2_kernel(
    const float* __restrict__ Wd, const float* __restrict__ bd)
{
    int e = blockIdx.z;
    int cnt = g_cnt[e];
    int row0 = blockIdx.y * 64;
    if (row0 >= cnt) return;
    int col0 = blockIdx.x * 64;

    __shared__ float sH[16][64];
    __shared__ float sW[16][64];

    int tid = threadIdx.x;
    int ty = tid >> 4, tx = tid & 15;
    int base = g_off[e];
    const float* WdE = Wd + (size_t)e * FDIM * DDIM;

    float acc[4][4];
#pragma unroll
    for (int i = 0; i < 4; i++)
#pragma unroll
        for (int j = 0; j < 4; j++) acc[i][j] = 0.f;

    int lm = tid >> 2;
    int lk = (tid & 3) * 4;

    for (int kb = 0; kb < FDIM; kb += 16) {
        {
            int r = min(row0 + lm, cnt - 1);
            float4 v = *(const float4*)(g_H + (size_t)(base + r) * FDIM + kb + lk);
            sH[lk + 0][lm] = v.x; sH[lk + 1][lm] = v.y;
            sH[lk + 2][lm] = v.z; sH[lk + 3][lm] = v.w;
        }
        {
            int idx = tid * 4;
            int k = idx >> 6, n = idx & 63;
            *(float4*)&sW[k][n] = *(const float4*)(WdE + (size_t)(kb + k) * DDIM + col0 + n);
        }
        __syncthreads();
#pragma unroll
        for (int k = 0; k < 16; k++) {
            float a[4], b[4];
            *(float4*)a = *(const float4*)&sH[k][ty * 4];
            *(float4*)b = *(const float4*)&sW[k][tx * 4];
#pragma unroll
            for (int i = 0; i < 4; i++)
#pragma unroll
                for (int j = 0; j < 4; j++) acc[i][j] += a[i] * b[j];
        }
        __syncthreads();
    }

#pragma unroll
    for (int i = 0; i < 4; i++) {
        int r = row0 + ty * 4 + i;
        if (r >= cnt) break;
        float w  = g_wp [e * T_TOK + r];
        int  dst = g_dst[e * T_TOK + r];
        float* orow = g_pout + (size_t)dst * DDIM + col0;
        float4 ov;
        float* op = (float*)&ov;
#pragma unroll
        for (int j = 0; j < 4; j++) {
            int n = col0 + tx * 4 + j;
            op[j] = w * (acc[i][j] + bd[e * DDIM + n]);
        }
        *(float4*)&orow[tx * 4] = ov;
    }
}

// ---------------- combine: out[t] = pout[2t] + pout[2t+1] ------------------
__global__ __launch_bounds__(256) void combine_kernel(float* __restrict__ out)
{
    size_t v = (size_t)blockIdx.x * blockDim.x + threadIdx.x;  // float4 index
    size_t t = v / (DDIM / 4);
    size_t c = v % (DDIM / 4);
    if (t >= T_TOK) return;
    const float4* p0 = (const float4*)(g_pout + (2 * t)     * (size_t)DDIM) + c;
    const float4* p1 = (const float4*)(g_pout + (2 * t + 1) * (size_t)DDIM) + c;
    float4 a = *p0, b = *p1;
    float4 o;
    o.x = a.x + b.x; o.y = a.y + b.y; o.z = a.z + b.z; o.w = a.w + b.w;
    ((float4*)out)[v] = o;
}

// ---------------- launch ---------------------------------------------------
extern "C" void kernel_launch(void* const* d_in, const int* in_sizes, int n_in,
                              void* d_out, int out_size)
{
    const float* x      = (const float*)d_in[0];
    const float* gate_w = (const float*)d_in[1];
    const float* gate_b = (const float*)d_in[2];
    const float* Wg     = (const float*)d_in[3];
    const float* bg     = (const float*)d_in[4];
    const float* Wu     = (const float*)d_in[5];
    const float* bu     = (const float*)d_in[6];
    const float* Wd     = (const float*)d_in[7];
    const float* bd     = (const float*)d_in[8];
    float* out = (float*)d_out;

    int write_logits = (out_size >= T_TOK * DDIM + T_TOK * NE) ? 1 : 0;

    zero_cnt_kernel<<<1, 32>>>();
    router_kernel<<<T_TOK / 8, 256>>>(x, gate_w, gate_b,
                                      out + (size_t)T_TOK * DDIM, write_logits);
    offsets_kernel<<<1, 32>>>();
    gemm1_kernel<<<dim3(FDIM / 64, T_TOK / 64, NE), 256>>>(x, Wg, bg, Wu, bu);
    gemm2_kernel<<<dim3(DDIM / 64, T_TOK / 64, NE), 256>>>(Wd, bd);
    combine_kernel<<<(T_TOK * (DDIM / 4)) / 256, 256>>>(out);
}